// round 5
// baseline (speedup 1.0000x reference)
#include <cuda_runtime.h>
#include <cuda_bf16.h>

// ----------------------------------------------------------------------------
// rlf_53446573032131: hypernetwork
//   trunk(map[idx]) -> z(32)  [only 64 distinct maps!]
//   theta_e = z@e_w+e_b (5456), theta_f = z@f_w+f_b (21768)  [per map]
//   per sample: e-MLP(S), e-MLP(G) -> zf(32) -> f-MLP -> ang(8) -> sin/cos(16)
//
// Strategy:
//   K1 zero counts, K2 group samples by map (atomic lists)
//   K3 trunk for 64 maps -> g_z
//   K4 theta_e/theta_f for 64 maps -> g_te/g_tf (7 MB, L2 resident)
//   K5 main: CTA = (map, block of 32 samples); lanes = samples -> all weight
//      loads warp-uniform (LDG.128 broadcast); activations staged transposed
//      in smem (conflict-free); warps split output neurons (no duplication).
// ----------------------------------------------------------------------------

#define NMAPS 64
#define BSZ   8192
#define CAP   512          // per-map sample list capacity (mean 128, >30 sigma)

// theta_e layout (in=2, sz=[64,64,16]):
//   W1e@0 [2][64] | b1e@128 | W2e@192 [64][64] | b2e@4288 | W3e@4352 [64][16] | b3e@5376
// theta_f layout (in=32, sz=[128,128,8]):
//   W1f@0 [32][128] | b1f@4096 | W2f@4224 [128][128] | b2f@20608 | W3f@20736 [128][8] | b3f@21760
#define TE_SZ 5456
#define TF_SZ 21768

__device__ int   g_count[NMAPS];
__device__ int   g_list[NMAPS * CAP];
__device__ float g_z[NMAPS * 32];
__device__ float g_te[NMAPS * TE_SZ];
__device__ float g_tf[NMAPS * TF_SZ];

__device__ __forceinline__ float leaky(float x) {
    // x>=0: max(x,0.2x)=x ; x<0: max(x,0.2x)=0.2x
    return fmaxf(x, 0.2f * x);
}

// ---------------------------------------------------------------- grouping --
__global__ void zero_counts_kernel() {
    if (threadIdx.x < NMAPS) g_count[threadIdx.x] = 0;
}

__global__ void build_lists_kernel(const int* __restrict__ indices) {
    int b = blockIdx.x * 256 + threadIdx.x;
    if (b < BSZ) {
        int m = indices[b];
        int pos = atomicAdd(&g_count[m], 1);
        if (pos < CAP) g_list[m * CAP + pos] = b;
    }
}

// ------------------------------------------------------------------- trunk --
// One CTA (256 threads) per map. maps C=1 so transpose(0,2,3,1) is identity
// on the flattened 1024 vector.
__global__ __launch_bounds__(256) void trunk_kernel(
    const float* __restrict__ maps,
    const float* __restrict__ fc1_w, const float* __restrict__ fc1_b,
    const float* __restrict__ fc2_w, const float* __restrict__ fc2_b,
    const float* __restrict__ fc3_w, const float* __restrict__ fc3_b,
    const float* __restrict__ bn_w,  const float* __restrict__ bn_b)
{
    int m   = blockIdx.x;
    int tid = threadIdx.x;

    __shared__ float ms[1024];
    __shared__ float red[4 * 256];
    __shared__ float a1[256];
    __shared__ float a2[128];
    __shared__ float a3[128];

    for (int i = tid; i < 1024; i += 256) ms[i] = maps[m * 1024 + i];
    __syncthreads();

    // L1: 1024 -> 256. thread = (output-group of 4, i-partition of 256)
    {
        int og = tid & 63;       // outputs 4*og .. 4*og+3
        int ip = tid >> 6;       // 0..3
        float c0 = 0.f, c1 = 0.f, c2 = 0.f, c3 = 0.f;
        int i0 = ip * 256;
        #pragma unroll 4
        for (int i = i0; i < i0 + 256; i++) {
            float x = ms[i];
            float4 w = *(const float4*)(fc1_w + i * 256 + 4 * og);
            c0 += x * w.x; c1 += x * w.y; c2 += x * w.z; c3 += x * w.w;
        }
        red[ip * 256 + 4 * og + 0] = c0;
        red[ip * 256 + 4 * og + 1] = c1;
        red[ip * 256 + 4 * og + 2] = c2;
        red[ip * 256 + 4 * og + 3] = c3;
    }
    __syncthreads();
    {
        float s = red[tid] + red[256 + tid] + red[512 + tid] + red[768 + tid]
                + fc1_b[tid];
        a1[tid] = leaky(s);
    }
    __syncthreads();

    // L2: 256 -> 128
    if (tid < 128) {
        float c0 = 0.f, c1 = 0.f, c2 = 0.f, c3 = 0.f;
        #pragma unroll 4
        for (int i = 0; i < 256; i += 4) {
            c0 += a1[i + 0] * fc2_w[(i + 0) * 128 + tid];
            c1 += a1[i + 1] * fc2_w[(i + 1) * 128 + tid];
            c2 += a1[i + 2] * fc2_w[(i + 2) * 128 + tid];
            c3 += a1[i + 3] * fc2_w[(i + 3) * 128 + tid];
        }
        a2[tid] = leaky(c0 + c1 + c2 + c3 + fc2_b[tid]);
    }
    __syncthreads();

    // L3: 128 -> 128
    if (tid < 128) {
        float c0 = 0.f, c1 = 0.f, c2 = 0.f, c3 = 0.f;
        #pragma unroll 4
        for (int i = 0; i < 128; i += 4) {
            c0 += a2[i + 0] * fc3_w[(i + 0) * 128 + tid];
            c1 += a2[i + 1] * fc3_w[(i + 1) * 128 + tid];
            c2 += a2[i + 2] * fc3_w[(i + 2) * 128 + tid];
            c3 += a2[i + 3] * fc3_w[(i + 3) * 128 + tid];
        }
        a3[tid] = leaky(c0 + c1 + c2 + c3 + fc3_b[tid]);
    }
    __syncthreads();

    // L4 (bn): 128 -> 32, NO activation
    if (tid < 32) {
        float c0 = 0.f, c1 = 0.f, c2 = 0.f, c3 = 0.f;
        #pragma unroll 4
        for (int i = 0; i < 128; i += 4) {
            c0 += a3[i + 0] * bn_w[(i + 0) * 32 + tid];
            c1 += a3[i + 1] * bn_w[(i + 1) * 32 + tid];
            c2 += a3[i + 2] * bn_w[(i + 2) * 32 + tid];
            c3 += a3[i + 3] * bn_w[(i + 3) * 32 + tid];
        }
        g_z[m * 32 + tid] = c0 + c1 + c2 + c3 + bn_b[tid];
    }
}

// ------------------------------------------------------------------- theta --
// Thread j owns one theta column across ALL 64 maps: the 32 weight values are
// read ONCE into registers and reused 64x (w read total = 3.5 MB from DRAM).
__global__ __launch_bounds__(128) void theta_kernel(
    const float* __restrict__ e_w, const float* __restrict__ e_b,
    const float* __restrict__ f_w, const float* __restrict__ f_b)
{
    __shared__ float sz[NMAPS * 32];
    int tid = threadIdx.x;
    for (int i = tid; i < NMAPS * 32; i += 128) sz[i] = g_z[i];
    __syncthreads();

    int j = blockIdx.x * 128 + tid;
    const float* W; const float* Bv; float* dst; int ncol; int jj;
    if (j < TE_SZ) { W = e_w; Bv = e_b; dst = g_te; ncol = TE_SZ; jj = j; }
    else {
        jj = j - TE_SZ;
        if (jj >= TF_SZ) return;
        W = f_w; Bv = f_b; dst = g_tf; ncol = TF_SZ;
    }

    float w[32];
    #pragma unroll
    for (int k = 0; k < 32; k++) w[k] = W[k * ncol + jj];
    float bb = Bv[jj];

    for (int m = 0; m < NMAPS; m++) {
        const float4* zr = (const float4*)(sz + m * 32);
        float c0 = bb, c1 = 0.f, c2 = 0.f, c3 = 0.f;
        #pragma unroll
        for (int kk = 0; kk < 8; kk++) {
            float4 z4 = zr[kk];
            c0 += z4.x * w[4 * kk + 0];
            c1 += z4.y * w[4 * kk + 1];
            c2 += z4.z * w[4 * kk + 2];
            c3 += z4.w * w[4 * kk + 3];
        }
        dst[m * ncol + jj] = c0 + c1 + c2 + c3;
    }
}

// -------------------------------------------------------------------- main --
// CTA = (map m, block of 32 samples). 128 threads = 4 warps.
//   lane (0..31)  = sample within block
//   q = warp id:  q>>1 selects stream (0: S, 1: G) for the e-phase
//                 q&1 selects output half for e-layers; q selects quarter for f
// Activations staged transposed in smem: act[feature][sample-column] so every
// LDS is consecutive across lanes (conflict-free); every weight load is
// warp-uniform LDG.128 (broadcast, L2-resident).
__global__ __launch_bounds__(128) void hyper_kernel(
    const float* __restrict__ states, float* __restrict__ out)
{
    int m = blockIdx.x;
    int cnt = g_count[m]; if (cnt > CAP) cnt = CAP;
    int base = blockIdx.y * 32;
    if (base >= cnt) return;

    int tid  = threadIdx.x;
    int lane = tid & 31;
    int q    = tid >> 5;
    int sidx = base + lane;
    bool valid = sidx < cnt;
    int b = g_list[m * CAP + (valid ? sidx : base)];

    const float* te = g_te + m * TE_SZ;
    const float* tf = g_tf + m * TF_SZ;

    __shared__ float sA[64 * 64];     // e activations, [feat][64 cols: S|G]
    __shared__ float sZ[32 * 32];     // zf, [feat][32 samples]
    __shared__ float sB[128 * 32];    // f1 activations, [feat][32 samples]
    __shared__ float sAng[4 * 8 * 32];

    int col = lane + ((q >> 1) << 5);           // 0..63 (S cols 0-31, G 32-63)
    float x0, x1;
    {
        const float* st = states + 4 * b + ((q >= 2) ? 2 : 0);
        x0 = st[0]; x1 = st[1];
    }
    int jh = (q & 1) * 32;

    // ---- e1: 2 -> 64 (leaky) ----
    #pragma unroll
    for (int j0 = 0; j0 < 32; j0 += 4) {
        int j = jh + j0;
        float4 w0 = *(const float4*)(te + j);
        float4 w1 = *(const float4*)(te + 64 + j);
        float4 bb = *(const float4*)(te + 128 + j);
        sA[(j + 0) * 64 + col] = leaky(bb.x + x0 * w0.x + x1 * w1.x);
        sA[(j + 1) * 64 + col] = leaky(bb.y + x0 * w0.y + x1 * w1.y);
        sA[(j + 2) * 64 + col] = leaky(bb.z + x0 * w0.z + x1 * w1.z);
        sA[(j + 3) * 64 + col] = leaky(bb.w + x0 * w0.w + x1 * w1.w);
    }
    __syncthreads();

    // ---- e2: 64 -> 64 (leaky) ----
    float a[64];
    #pragma unroll
    for (int k = 0; k < 64; k++) a[k] = sA[k * 64 + col];
    __syncthreads();   // all reads done before sA is overwritten
    #pragma unroll 2
    for (int j0 = 0; j0 < 32; j0 += 4) {
        int j = jh + j0;
        float4 bb = *(const float4*)(te + 4288 + j);
        float c0 = bb.x, c1 = bb.y, c2 = bb.z, c3 = bb.w;
        #pragma unroll
        for (int k = 0; k < 64; k++) {
            float4 w = *(const float4*)(te + 192 + k * 64 + j);
            c0 += a[k] * w.x; c1 += a[k] * w.y;
            c2 += a[k] * w.z; c3 += a[k] * w.w;
        }
        sA[(j + 0) * 64 + col] = leaky(c0);
        sA[(j + 1) * 64 + col] = leaky(c1);
        sA[(j + 2) * 64 + col] = leaky(c2);
        sA[(j + 3) * 64 + col] = leaky(c3);
    }
    __syncthreads();

    // ---- e3: 64 -> 16 (NO activation), write zf ----
    #pragma unroll
    for (int k = 0; k < 64; k++) a[k] = sA[k * 64 + col];
    {
        int jb = (q & 1) * 8;
        #pragma unroll
        for (int j0 = 0; j0 < 8; j0 += 4) {
            int j = jb + j0;
            float4 bb = *(const float4*)(te + 5376 + j);
            float c0 = bb.x, c1 = bb.y, c2 = bb.z, c3 = bb.w;
            #pragma unroll
            for (int k = 0; k < 64; k++) {
                float4 w = *(const float4*)(te + 4352 + k * 16 + j);
                c0 += a[k] * w.x; c1 += a[k] * w.y;
                c2 += a[k] * w.z; c3 += a[k] * w.w;
            }
            int f = j + ((q >> 1) ? 16 : 0);   // e_s -> zf[0:16], e_g -> zf[16:32]
            sZ[(f + 0) * 32 + lane] = c0;
            sZ[(f + 1) * 32 + lane] = c1;
            sZ[(f + 2) * 32 + lane] = c2;
            sZ[(f + 3) * 32 + lane] = c3;
        }
    }
    __syncthreads();

    // ---- f1: 32 -> 128 (leaky). warp q owns outputs [32q, 32q+32) ----
    float zf[32];
    #pragma unroll
    for (int k = 0; k < 32; k++) zf[k] = sZ[k * 32 + lane];
    int jf = q * 32;
    #pragma unroll 2
    for (int j0 = 0; j0 < 32; j0 += 4) {
        int j = jf + j0;
        float4 bb = *(const float4*)(tf + 4096 + j);
        float c0 = bb.x, c1 = bb.y, c2 = bb.z, c3 = bb.w;
        #pragma unroll
        for (int k = 0; k < 32; k++) {
            float4 w = *(const float4*)(tf + k * 128 + j);
            c0 += zf[k] * w.x; c1 += zf[k] * w.y;
            c2 += zf[k] * w.z; c3 += zf[k] * w.w;
        }
        sB[(j + 0) * 32 + lane] = leaky(c0);
        sB[(j + 1) * 32 + lane] = leaky(c1);
        sB[(j + 2) * 32 + lane] = leaky(c2);
        sB[(j + 3) * 32 + lane] = leaky(c3);
    }
    __syncthreads();

    // ---- f2: 128 -> 128 (leaky), fused with f3: 128 -> 8 (no activation) ----
    float h1[128];
    #pragma unroll
    for (int k = 0; k < 128; k++) h1[k] = sB[k * 32 + lane];
    float ang[8];
    #pragma unroll
    for (int r = 0; r < 8; r++) ang[r] = 0.f;

    for (int j0 = 0; j0 < 32; j0 += 4) {
        int j = jf + j0;
        float4 bb = *(const float4*)(tf + 20608 + j);
        float c0 = bb.x, c1 = bb.y, c2 = bb.z, c3 = bb.w;
        #pragma unroll
        for (int k = 0; k < 128; k++) {
            float4 w = *(const float4*)(tf + 4224 + k * 128 + j);
            c0 += h1[k] * w.x; c1 += h1[k] * w.y;
            c2 += h1[k] * w.z; c3 += h1[k] * w.w;
        }
        float h2[4] = { leaky(c0), leaky(c1), leaky(c2), leaky(c3) };
        #pragma unroll
        for (int t = 0; t < 4; t++) {
            float4 wa = *(const float4*)(tf + 20736 + (j + t) * 8);
            float4 wb = *(const float4*)(tf + 20736 + (j + t) * 8 + 4);
            ang[0] += h2[t] * wa.x; ang[1] += h2[t] * wa.y;
            ang[2] += h2[t] * wa.z; ang[3] += h2[t] * wa.w;
            ang[4] += h2[t] * wb.x; ang[5] += h2[t] * wb.y;
            ang[6] += h2[t] * wb.z; ang[7] += h2[t] * wb.w;
        }
    }

    #pragma unroll
    for (int r = 0; r < 8; r++) sAng[(q * 8 + r) * 32 + lane] = ang[r];
    __syncthreads();

    if (valid) {
        #pragma unroll
        for (int rr = 0; rr < 2; rr++) {
            int r = 2 * q + rr;
            float s = sAng[(0 + r) * 32 + lane]
                    + sAng[(8 + r) * 32 + lane]
                    + sAng[(16 + r) * 32 + lane]
                    + sAng[(24 + r) * 32 + lane]
                    + tf[21760 + r];
            out[b * 16 + r]     = sinf(s);
            out[b * 16 + 8 + r] = cosf(s);
        }
    }
}

// ----------------------------------------------------------------- launch --
extern "C" void kernel_launch(void* const* d_in, const int* in_sizes, int n_in,
                              void* d_out, int out_size)
{
    const int*   indices = (const int*)  d_in[0];
    const float* states  = (const float*)d_in[1];
    const float* maps    = (const float*)d_in[2];
    const float* fc1_w   = (const float*)d_in[3];
    const float* fc1_b   = (const float*)d_in[4];
    const float* fc2_w   = (const float*)d_in[5];
    const float* fc2_b   = (const float*)d_in[6];
    const float* fc3_w   = (const float*)d_in[7];
    const float* fc3_b   = (const float*)d_in[8];
    const float* bn_w    = (const float*)d_in[9];
    const float* bn_b    = (const float*)d_in[10];
    const float* e_w     = (const float*)d_in[11];
    const float* e_b     = (const float*)d_in[12];
    const float* f_w     = (const float*)d_in[13];
    const float* f_b     = (const float*)d_in[14];
    float* out = (float*)d_out;

    zero_counts_kernel<<<1, 64>>>();
    build_lists_kernel<<<(BSZ + 255) / 256, 256>>>(indices);
    trunk_kernel<<<NMAPS, 256>>>(maps, fc1_w, fc1_b, fc2_w, fc2_b,
                                 fc3_w, fc3_b, bn_w, bn_b);
    theta_kernel<<<(TE_SZ + TF_SZ + 127) / 128, 128>>>(e_w, e_b, f_w, f_b);
    hyper_kernel<<<dim3(NMAPS, CAP / 32), 128>>>(states, out);
}

// round 6
// speedup vs baseline: 1.1126x; 1.1126x over previous
#include <cuda_runtime.h>
#include <cuda_bf16.h>

// ----------------------------------------------------------------------------
// rlf_53446573032131: hypernetwork (R6)
//   K1 zero counts, K2 group samples by map
//   K3a trunk L1 (tiled multi-map GEMM), K3b trunk L2-L4 per map -> g_z
//   K4 theta_e/theta_f for 64 maps (map-parallel, 8 maps/thread)
//   K5 hyper: CTA = (map, 32 samples), 256 threads / 8 warps, packed FFMA2,
//      activations ping-ponged through smem (conflict-free LDS).
// ----------------------------------------------------------------------------

#define NMAPS 64
#define BSZ   8192
#define CAP   512

// theta_e (in=2, sz=[64,64,16]):
//   W1@0 [2][64] | b1@128 | W2@192 [64][64] | b2@4288 | W3@4352 [64][16] | b3@5376
// theta_f (in=32, sz=[128,128,8]):
//   W1@0 [32][128] | b1@4096 | W2@4224 [128][128] | b2@20608 | W3@20736 [128][8] | b3@21760
#define TE_SZ 5456
#define TF_SZ 21768

__device__ int   g_count[NMAPS];
__device__ int   g_list[NMAPS * CAP];
__device__ __align__(16) float g_a1[NMAPS * 256];
__device__ __align__(16) float g_z[NMAPS * 32];
__device__ __align__(16) float g_te[NMAPS * TE_SZ];
__device__ __align__(16) float g_tf[NMAPS * TF_SZ];

typedef unsigned long long u64;

__device__ __forceinline__ float leaky(float x) { return fmaxf(x, 0.2f * x); }

// ---- packed f32x2 helpers (Blackwell FFMA2 path) ----
__device__ __forceinline__ void ffma2(u64& d, u64 a, u64 b) {
    asm("fma.rn.f32x2 %0, %1, %2, %0;" : "+l"(d) : "l"(a), "l"(b));
}
__device__ __forceinline__ u64 pack2(float x) {
    u64 r; asm("mov.b64 %0, {%1, %1};" : "=l"(r) : "f"(x)); return r;
}
__device__ __forceinline__ float2 unpack2(u64 v) {
    float2 r; asm("mov.b64 {%0, %1}, %2;" : "=f"(r.x), "=f"(r.y) : "l"(v)); return r;
}

// ---------------------------------------------------------------- grouping --
__global__ void zero_counts_kernel() {
    if (threadIdx.x < NMAPS) g_count[threadIdx.x] = 0;
}

__global__ void build_lists_kernel(const int* __restrict__ indices) {
    int b = blockIdx.x * 256 + threadIdx.x;
    if (b < BSZ) {
        int m = indices[b];
        int pos = atomicAdd(&g_count[m], 1);
        if (pos < CAP) g_list[m * CAP + pos] = b;
    }
}

// ---------------------------------------------------------------- trunk L1 --
// grid (4 output-tiles of 64, 16 map-tiles of 4). Each weight load feeds 4
// maps (4 FMA / LDG); fc1_w total traffic 16 MB (L2).
__global__ __launch_bounds__(256) void trunk1_kernel(
    const float* __restrict__ maps,
    const float* __restrict__ fc1_w, const float* __restrict__ fc1_b)
{
    __shared__ float ms[4 * 1024];
    __shared__ float red[4 * 64 * 4];
    int ot = blockIdx.x, mg = blockIdx.y;
    int tid = threadIdx.x;

    for (int i = tid; i < 4096; i += 256) ms[i] = maps[mg * 4096 + i];
    __syncthreads();

    int ol = tid & 63, part = tid >> 6;
    int o = ot * 64 + ol;
    float a0 = 0.f, a1 = 0.f, a2 = 0.f, a3 = 0.f;
    int i0 = part * 256;
    #pragma unroll 4
    for (int i = i0; i < i0 + 256; i++) {
        float w = fc1_w[i * 256 + o];
        a0 += ms[i] * w;
        a1 += ms[1024 + i] * w;
        a2 += ms[2048 + i] * w;
        a3 += ms[3072 + i] * w;
    }
    int rb = (part * 64 + ol) * 4;
    red[rb + 0] = a0; red[rb + 1] = a1; red[rb + 2] = a2; red[rb + 3] = a3;
    __syncthreads();

    int o2 = tid >> 2, mm = tid & 3;
    float s = red[o2 * 4 + mm] + red[(64 + o2) * 4 + mm]
            + red[(128 + o2) * 4 + mm] + red[(192 + o2) * 4 + mm]
            + fc1_b[ot * 64 + o2];
    g_a1[(mg * 4 + mm) * 256 + ot * 64 + o2] = leaky(s);
}

// ------------------------------------------------------------- trunk L2-L4 --
__global__ __launch_bounds__(128) void trunk2_kernel(
    const float* __restrict__ fc2_w, const float* __restrict__ fc2_b,
    const float* __restrict__ fc3_w, const float* __restrict__ fc3_b,
    const float* __restrict__ bn_w,  const float* __restrict__ bn_b)
{
    int m = blockIdx.x, tid = threadIdx.x;
    __shared__ float a1[256];
    __shared__ float a2[128];
    __shared__ float a3[128];

    for (int i = tid; i < 256; i += 128) a1[i] = g_a1[m * 256 + i];
    __syncthreads();

    {   // L2: 256 -> 128
        float c0 = 0.f, c1 = 0.f, c2 = 0.f, c3 = 0.f;
        #pragma unroll 4
        for (int i = 0; i < 256; i += 4) {
            c0 += a1[i + 0] * fc2_w[(i + 0) * 128 + tid];
            c1 += a1[i + 1] * fc2_w[(i + 1) * 128 + tid];
            c2 += a1[i + 2] * fc2_w[(i + 2) * 128 + tid];
            c3 += a1[i + 3] * fc2_w[(i + 3) * 128 + tid];
        }
        a2[tid] = leaky(c0 + c1 + c2 + c3 + fc2_b[tid]);
    }
    __syncthreads();

    {   // L3: 128 -> 128
        float c0 = 0.f, c1 = 0.f, c2 = 0.f, c3 = 0.f;
        #pragma unroll 4
        for (int i = 0; i < 128; i += 4) {
            c0 += a2[i + 0] * fc3_w[(i + 0) * 128 + tid];
            c1 += a2[i + 1] * fc3_w[(i + 1) * 128 + tid];
            c2 += a2[i + 2] * fc3_w[(i + 2) * 128 + tid];
            c3 += a2[i + 3] * fc3_w[(i + 3) * 128 + tid];
        }
        a3[tid] = leaky(c0 + c1 + c2 + c3 + fc3_b[tid]);
    }
    __syncthreads();

    if (tid < 32) {  // L4 (bn): 128 -> 32, no activation
        float c0 = 0.f, c1 = 0.f, c2 = 0.f, c3 = 0.f;
        #pragma unroll 4
        for (int i = 0; i < 128; i += 4) {
            c0 += a3[i + 0] * bn_w[(i + 0) * 32 + tid];
            c1 += a3[i + 1] * bn_w[(i + 1) * 32 + tid];
            c2 += a3[i + 2] * bn_w[(i + 2) * 32 + tid];
            c3 += a3[i + 3] * bn_w[(i + 3) * 32 + tid];
        }
        g_z[m * 32 + tid] = c0 + c1 + c2 + c3 + bn_b[tid];
    }
}

// ------------------------------------------------------------------- theta --
// grid (213 col-blocks, 8 map-groups). Thread owns one column x 8 maps:
// 8x more threads than R5 (the occ=8.9% fix); weights re-read 8x = 28 MB L2.
__global__ __launch_bounds__(128) void theta_kernel(
    const float* __restrict__ e_w, const float* __restrict__ e_b,
    const float* __restrict__ f_w, const float* __restrict__ f_b)
{
    __shared__ float sz[8 * 32];
    int tid = threadIdx.x;
    int m0 = blockIdx.y * 8;
    for (int i = tid; i < 8 * 32; i += 128) sz[i] = g_z[m0 * 32 + i];
    __syncthreads();

    int j = blockIdx.x * 128 + tid;
    const float* W; const float* Bv; float* dst; int ncol; int jj;
    if (j < TE_SZ) { W = e_w; Bv = e_b; dst = g_te; ncol = TE_SZ; jj = j; }
    else {
        jj = j - TE_SZ;
        if (jj >= TF_SZ) return;
        W = f_w; Bv = f_b; dst = g_tf; ncol = TF_SZ;
    }

    float w[32];
    #pragma unroll
    for (int k = 0; k < 32; k++) w[k] = W[k * ncol + jj];
    float bb = Bv[jj];

    #pragma unroll
    for (int mm = 0; mm < 8; mm++) {
        const float4* zr = (const float4*)(sz + mm * 32);
        float c0 = bb, c1 = 0.f, c2 = 0.f, c3 = 0.f;
        #pragma unroll
        for (int kk = 0; kk < 8; kk++) {
            float4 z4 = zr[kk];
            c0 += z4.x * w[4 * kk + 0];
            c1 += z4.y * w[4 * kk + 1];
            c2 += z4.z * w[4 * kk + 2];
            c3 += z4.w * w[4 * kk + 3];
        }
        dst[(m0 + mm) * ncol + jj] = c0 + c1 + c2 + c3;
    }
}

// -------------------------------------------------------------------- main --
// CTA = (map, 32 samples), 256 threads / 8 warps.
//   lane = sample; e-phase: warp q -> stream st=q>>2, outputs (q&3)*16..+16
//   f-phase: warp q -> outputs q*16..+16; final 8-way reduce of ang partials.
// All weight loads warp-uniform LDG.128 (L2 broadcast); all activation traffic
// via conflict-free LDS; all inner products use packed FFMA2 (fma.rn.f32x2).
// smem ping-pong: e1->sA, e2: sA->sB, e3: sB->sZ, f1: sZ->sA, f2: sA->sAng.
__global__ __launch_bounds__(256) void hyper_kernel(
    const float* __restrict__ states, float* __restrict__ out)
{
    int m = blockIdx.x;
    int cnt = g_count[m]; if (cnt > CAP) cnt = CAP;
    int base = blockIdx.y * 32;
    if (base >= cnt) return;

    int tid  = threadIdx.x;
    int lane = tid & 31;
    int q    = tid >> 5;
    int st   = q >> 2;          // e-stream: 0 = S, 1 = G
    int qq   = q & 3;
    int sidx = base + lane;
    bool valid = sidx < cnt;
    int b = g_list[m * CAP + (valid ? sidx : base)];

    const float* te = g_te + m * TE_SZ;
    const float* tf = g_tf + m * TF_SZ;

    __shared__ float sA[4096];     // 64x64 e-act / 128x32 f-act (reused)
    __shared__ float sB[4096];     // 64x64 e2 out (reused)
    __shared__ float sZ[1024];     // zf 32x32
    __shared__ float sAng[2048];   // 8 warps x 8 ang x 32 lanes

    int col = lane + st * 32;
    float2 xv = *(const float2*)(states + 4 * b + st * 2);
    int jh = qq * 16;

    // ---- e1: 2 -> 64 (leaky) ----
    #pragma unroll
    for (int j0 = 0; j0 < 16; j0 += 4) {
        int j = jh + j0;
        float4 w0 = *(const float4*)(te + j);
        float4 w1 = *(const float4*)(te + 64 + j);
        float4 bb = *(const float4*)(te + 128 + j);
        sA[(j + 0) * 64 + col] = leaky(fmaf(xv.x, w0.x, fmaf(xv.y, w1.x, bb.x)));
        sA[(j + 1) * 64 + col] = leaky(fmaf(xv.x, w0.y, fmaf(xv.y, w1.y, bb.y)));
        sA[(j + 2) * 64 + col] = leaky(fmaf(xv.x, w0.z, fmaf(xv.y, w1.z, bb.z)));
        sA[(j + 3) * 64 + col] = leaky(fmaf(xv.x, w0.w, fmaf(xv.y, w1.w, bb.w)));
    }
    __syncthreads();

    // ---- e2: 64 -> 64 (leaky), sA -> sB ----
    #pragma unroll
    for (int j0 = 0; j0 < 16; j0 += 8) {
        int j = jh + j0;
        ulonglong2 b01 = *(const ulonglong2*)(te + 4288 + j);
        ulonglong2 b23 = *(const ulonglong2*)(te + 4288 + j + 4);
        u64 a0 = b01.x, a1 = b01.y, a2 = b23.x, a3 = b23.y;
        #pragma unroll 16
        for (int k = 0; k < 64; k++) {
            u64 hh = pack2(sA[k * 64 + col]);
            const float* wp = te + 192 + k * 64 + j;
            ulonglong2 w01 = *(const ulonglong2*)(wp);
            ulonglong2 w23 = *(const ulonglong2*)(wp + 4);
            ffma2(a0, hh, w01.x); ffma2(a1, hh, w01.y);
            ffma2(a2, hh, w23.x); ffma2(a3, hh, w23.y);
        }
        float2 r;
        r = unpack2(a0); sB[(j + 0) * 64 + col] = leaky(r.x); sB[(j + 1) * 64 + col] = leaky(r.y);
        r = unpack2(a1); sB[(j + 2) * 64 + col] = leaky(r.x); sB[(j + 3) * 64 + col] = leaky(r.y);
        r = unpack2(a2); sB[(j + 4) * 64 + col] = leaky(r.x); sB[(j + 5) * 64 + col] = leaky(r.y);
        r = unpack2(a3); sB[(j + 6) * 64 + col] = leaky(r.x); sB[(j + 7) * 64 + col] = leaky(r.y);
    }
    __syncthreads();

    // ---- e3: 64 -> 16 (no activation), sB -> sZ ----
    {
        int j = qq * 4;
        ulonglong2 bb = *(const ulonglong2*)(te + 5376 + j);
        u64 a0 = bb.x, a1 = bb.y;
        #pragma unroll 16
        for (int k = 0; k < 64; k++) {
            u64 hh = pack2(sB[k * 64 + col]);
            ulonglong2 w = *(const ulonglong2*)(te + 4352 + k * 16 + j);
            ffma2(a0, hh, w.x); ffma2(a1, hh, w.y);
        }
        int f = j + st * 16;   // e_s -> zf[0:16], e_g -> zf[16:32]
        float2 r;
        r = unpack2(a0); sZ[(f + 0) * 32 + lane] = r.x; sZ[(f + 1) * 32 + lane] = r.y;
        r = unpack2(a1); sZ[(f + 2) * 32 + lane] = r.x; sZ[(f + 3) * 32 + lane] = r.y;
    }
    __syncthreads();

    // ---- f1: 32 -> 128 (leaky), sZ -> sA (as 128x32) ----
    int jf = q * 16;
    #pragma unroll
    for (int j0 = 0; j0 < 16; j0 += 8) {
        int j = jf + j0;
        ulonglong2 b01 = *(const ulonglong2*)(tf + 4096 + j);
        ulonglong2 b23 = *(const ulonglong2*)(tf + 4096 + j + 4);
        u64 a0 = b01.x, a1 = b01.y, a2 = b23.x, a3 = b23.y;
        #pragma unroll 8
        for (int k = 0; k < 32; k++) {
            u64 hh = pack2(sZ[k * 32 + lane]);
            const float* wp = tf + k * 128 + j;
            ulonglong2 w01 = *(const ulonglong2*)(wp);
            ulonglong2 w23 = *(const ulonglong2*)(wp + 4);
            ffma2(a0, hh, w01.x); ffma2(a1, hh, w01.y);
            ffma2(a2, hh, w23.x); ffma2(a3, hh, w23.y);
        }
        float2 r;
        r = unpack2(a0); sA[(j + 0) * 32 + lane] = leaky(r.x); sA[(j + 1) * 32 + lane] = leaky(r.y);
        r = unpack2(a1); sA[(j + 2) * 32 + lane] = leaky(r.x); sA[(j + 3) * 32 + lane] = leaky(r.y);
        r = unpack2(a2); sA[(j + 4) * 32 + lane] = leaky(r.x); sA[(j + 5) * 32 + lane] = leaky(r.y);
        r = unpack2(a3); sA[(j + 6) * 32 + lane] = leaky(r.x); sA[(j + 7) * 32 + lane] = leaky(r.y);
    }
    __syncthreads();

    // ---- f2: 128 -> 128 (leaky) fused with f3: 128 -> 8 partials ----
    u64 g01 = 0, g23 = 0, g45 = 0, g67 = 0;
    #pragma unroll
    for (int j0 = 0; j0 < 16; j0 += 8) {
        int j = jf + j0;
        ulonglong2 b01 = *(const ulonglong2*)(tf + 20608 + j);
        ulonglong2 b23 = *(const ulonglong2*)(tf + 20608 + j + 4);
        u64 a0 = b01.x, a1 = b01.y, a2 = b23.x, a3 = b23.y;
        #pragma unroll 16
        for (int k = 0; k < 128; k++) {
            u64 hh = pack2(sA[k * 32 + lane]);
            const float* wp = tf + 4224 + k * 128 + j;
            ulonglong2 w01 = *(const ulonglong2*)(wp);
            ulonglong2 w23 = *(const ulonglong2*)(wp + 4);
            ffma2(a0, hh, w01.x); ffma2(a1, hh, w01.y);
            ffma2(a2, hh, w23.x); ffma2(a3, hh, w23.y);
        }
        float h2[8];
        float2 r;
        r = unpack2(a0); h2[0] = leaky(r.x); h2[1] = leaky(r.y);
        r = unpack2(a1); h2[2] = leaky(r.x); h2[3] = leaky(r.y);
        r = unpack2(a2); h2[4] = leaky(r.x); h2[5] = leaky(r.y);
        r = unpack2(a3); h2[6] = leaky(r.x); h2[7] = leaky(r.y);
        #pragma unroll
        for (int t = 0; t < 8; t++) {
            u64 hh = pack2(h2[t]);
            const float* wp = tf + 20736 + (j + t) * 8;
            ulonglong2 wa = *(const ulonglong2*)(wp);
            ulonglong2 wb = *(const ulonglong2*)(wp + 4);
            ffma2(g01, hh, wa.x); ffma2(g23, hh, wa.y);
            ffma2(g45, hh, wb.x); ffma2(g67, hh, wb.y);
        }
    }
    {
        float2 r;
        r = unpack2(g01); sAng[(q * 8 + 0) * 32 + lane] = r.x; sAng[(q * 8 + 1) * 32 + lane] = r.y;
        r = unpack2(g23); sAng[(q * 8 + 2) * 32 + lane] = r.x; sAng[(q * 8 + 3) * 32 + lane] = r.y;
        r = unpack2(g45); sAng[(q * 8 + 4) * 32 + lane] = r.x; sAng[(q * 8 + 5) * 32 + lane] = r.y;
        r = unpack2(g67); sAng[(q * 8 + 6) * 32 + lane] = r.x; sAng[(q * 8 + 7) * 32 + lane] = r.y;
    }
    __syncthreads();

    // ---- reduce 8 partials, bias, sin/cos: warp q owns angle index q ----
    if (valid) {
        float s = tf[21760 + q];
        #pragma unroll
        for (int w = 0; w < 8; w++) s += sAng[(w * 8 + q) * 32 + lane];
        out[b * 16 + q]     = sinf(s);
        out[b * 16 + 8 + q] = cosf(s);
    }
}

// ----------------------------------------------------------------- launch --
extern "C" void kernel_launch(void* const* d_in, const int* in_sizes, int n_in,
                              void* d_out, int out_size)
{
    const int*   indices = (const int*)  d_in[0];
    const float* states  = (const float*)d_in[1];
    const float* maps    = (const float*)d_in[2];
    const float* fc1_w   = (const float*)d_in[3];
    const float* fc1_b   = (const float*)d_in[4];
    const float* fc2_w   = (const float*)d_in[5];
    const float* fc2_b   = (const float*)d_in[6];
    const float* fc3_w   = (const float*)d_in[7];
    const float* fc3_b   = (const float*)d_in[8];
    const float* bn_w    = (const float*)d_in[9];
    const float* bn_b    = (const float*)d_in[10];
    const float* e_w     = (const float*)d_in[11];
    const float* e_b     = (const float*)d_in[12];
    const float* f_w     = (const float*)d_in[13];
    const float* f_b     = (const float*)d_in[14];
    float* out = (float*)d_out;

    zero_counts_kernel<<<1, 64>>>();
    build_lists_kernel<<<(BSZ + 255) / 256, 256>>>(indices);
    trunk1_kernel<<<dim3(4, 16), 256>>>(maps, fc1_w, fc1_b);
    trunk2_kernel<<<NMAPS, 128>>>(fc2_w, fc2_b, fc3_w, fc3_b, bn_w, bn_b);
    theta_kernel<<<dim3((TE_SZ + TF_SZ + 127) / 128, 8), 128>>>(e_w, e_b, f_w, f_b);
    hyper_kernel<<<dim3(NMAPS, CAP / 32), 256>>>(states, out);
}

// round 7
// speedup vs baseline: 1.2678x; 1.1395x over previous
#include <cuda_runtime.h>
#include <cuda_bf16.h>

// ----------------------------------------------------------------------------
// rlf_53446573032131: hypernetwork (R7)
//   K1 trunk L1 (tiled multi-map GEMM) + zero counts
//   K2 group samples by map
//   K3 trunk L2-L4: block 512, i-partitioned dot products + smem reduce
//      (fixes R6's 35.8us latency-chain kernel: occ 5.5% -> ~25%)
//   K4 theta_e/theta_f for 64 maps (map-parallel)
//   K5 hyper: CTA = (map, 32 samples), 8 warps, packed FFMA2, fused
//      16-output accumulator batches (halves LDS/pack traffic vs R6)
// ----------------------------------------------------------------------------

#define NMAPS 64
#define BSZ   8192
#define CAP   512

// theta_e (in=2, sz=[64,64,16]):
//   W1@0 [2][64] | b1@128 | W2@192 [64][64] | b2@4288 | W3@4352 [64][16] | b3@5376
// theta_f (in=32, sz=[128,128,8]):
//   W1@0 [32][128] | b1@4096 | W2@4224 [128][128] | b2@20608 | W3@20736 [128][8] | b3@21760
#define TE_SZ 5456
#define TF_SZ 21768

__device__ int   g_count[NMAPS];
__device__ int   g_list[NMAPS * CAP];
__device__ __align__(16) float g_a1[NMAPS * 256];
__device__ __align__(16) float g_z[NMAPS * 32];
__device__ __align__(16) float g_te[NMAPS * TE_SZ];
__device__ __align__(16) float g_tf[NMAPS * TF_SZ];

typedef unsigned long long u64;

__device__ __forceinline__ float leaky(float x) { return fmaxf(x, 0.2f * x); }

// ---- packed f32x2 helpers (Blackwell FFMA2 path) ----
__device__ __forceinline__ void ffma2(u64& d, u64 a, u64 b) {
    asm("fma.rn.f32x2 %0, %1, %2, %0;" : "+l"(d) : "l"(a), "l"(b));
}
__device__ __forceinline__ u64 pack2(float x) {
    u64 r; asm("mov.b64 %0, {%1, %1};" : "=l"(r) : "f"(x)); return r;
}
__device__ __forceinline__ float2 unpack2(u64 v) {
    float2 r; asm("mov.b64 {%0, %1}, %2;" : "=f"(r.x), "=f"(r.y) : "l"(v)); return r;
}

// ---------------------------------------------------------------- grouping --
__global__ void build_lists_kernel(const int* __restrict__ indices) {
    int b = blockIdx.x * 256 + threadIdx.x;
    if (b < BSZ) {
        int m = indices[b];
        int pos = atomicAdd(&g_count[m], 1);
        if (pos < CAP) g_list[m * CAP + pos] = b;
    }
}

// ---------------------------------------------------------------- trunk L1 --
// grid (4 output-tiles of 64, 16 map-tiles of 4). Each weight load feeds 4
// maps. Also zeroes g_count (stream-ordered before build_lists).
__global__ __launch_bounds__(256) void trunk1_kernel(
    const float* __restrict__ maps,
    const float* __restrict__ fc1_w, const float* __restrict__ fc1_b)
{
    __shared__ float ms[4 * 1024];
    __shared__ float red[4 * 64 * 4];
    int ot = blockIdx.x, mg = blockIdx.y;
    int tid = threadIdx.x;

    if (ot == 0 && mg == 0 && tid < NMAPS) g_count[tid] = 0;

    for (int i = tid; i < 4096; i += 256) ms[i] = maps[mg * 4096 + i];
    __syncthreads();

    int ol = tid & 63, part = tid >> 6;
    int o = ot * 64 + ol;
    float a0 = 0.f, a1 = 0.f, a2 = 0.f, a3 = 0.f;
    int i0 = part * 256;
    #pragma unroll 4
    for (int i = i0; i < i0 + 256; i++) {
        float w = fc1_w[i * 256 + o];
        a0 += ms[i] * w;
        a1 += ms[1024 + i] * w;
        a2 += ms[2048 + i] * w;
        a3 += ms[3072 + i] * w;
    }
    int rb = (part * 64 + ol) * 4;
    red[rb + 0] = a0; red[rb + 1] = a1; red[rb + 2] = a2; red[rb + 3] = a3;
    __syncthreads();

    int o2 = tid >> 2, mm = tid & 3;
    float s = red[o2 * 4 + mm] + red[(64 + o2) * 4 + mm]
            + red[(128 + o2) * 4 + mm] + red[(192 + o2) * 4 + mm]
            + fc1_b[ot * 64 + o2];
    g_a1[(mg * 4 + mm) * 256 + ot * 64 + o2] = leaky(s);
}

// ------------------------------------------------------------- trunk L2-L4 --
// block 512: every output is computed by 4 partial-sum threads (16 for bn),
// cutting the dependent-load chain 4x-16x and raising warps 256 -> 1024.
__global__ __launch_bounds__(512) void trunk2_kernel(
    const float* __restrict__ fc2_w, const float* __restrict__ fc2_b,
    const float* __restrict__ fc3_w, const float* __restrict__ fc3_b,
    const float* __restrict__ bn_w,  const float* __restrict__ bn_b)
{
    int m = blockIdx.x, tid = threadIdx.x;
    __shared__ float a1[256];
    __shared__ float red[512];
    __shared__ float a2[128];
    __shared__ float a3[128];

    if (tid < 256) a1[tid] = g_a1[m * 256 + tid];
    __syncthreads();

    {   // L2: 256 -> 128, 4 i-partitions of 64
        int o = tid & 127, p = tid >> 7;
        float c0 = 0.f, c1 = 0.f, c2 = 0.f, c3 = 0.f;
        int i0 = p * 64;
        #pragma unroll
        for (int i = i0; i < i0 + 64; i += 4) {
            c0 += a1[i + 0] * fc2_w[(i + 0) * 128 + o];
            c1 += a1[i + 1] * fc2_w[(i + 1) * 128 + o];
            c2 += a1[i + 2] * fc2_w[(i + 2) * 128 + o];
            c3 += a1[i + 3] * fc2_w[(i + 3) * 128 + o];
        }
        red[p * 128 + o] = c0 + c1 + c2 + c3;
    }
    __syncthreads();
    if (tid < 128)
        a2[tid] = leaky(red[tid] + red[128 + tid] + red[256 + tid]
                        + red[384 + tid] + fc2_b[tid]);
    __syncthreads();

    {   // L3: 128 -> 128, 4 i-partitions of 32
        int o = tid & 127, p = tid >> 7;
        float c0 = 0.f, c1 = 0.f, c2 = 0.f, c3 = 0.f;
        int i0 = p * 32;
        #pragma unroll
        for (int i = i0; i < i0 + 32; i += 4) {
            c0 += a2[i + 0] * fc3_w[(i + 0) * 128 + o];
            c1 += a2[i + 1] * fc3_w[(i + 1) * 128 + o];
            c2 += a2[i + 2] * fc3_w[(i + 2) * 128 + o];
            c3 += a2[i + 3] * fc3_w[(i + 3) * 128 + o];
        }
        red[p * 128 + o] = c0 + c1 + c2 + c3;
    }
    __syncthreads();
    if (tid < 128)
        a3[tid] = leaky(red[tid] + red[128 + tid] + red[256 + tid]
                        + red[384 + tid] + fc3_b[tid]);
    __syncthreads();

    {   // L4 (bn): 128 -> 32, 16 i-partitions of 8, no activation
        int o = tid & 31, p = tid >> 5;
        float c = 0.f;
        #pragma unroll
        for (int i = p * 8; i < p * 8 + 8; i++)
            c += a3[i] * bn_w[i * 32 + o];
        red[p * 32 + o] = c;
    }
    __syncthreads();
    if (tid < 32) {
        float s = bn_b[tid];
        #pragma unroll
        for (int p = 0; p < 16; p++) s += red[p * 32 + tid];
        g_z[m * 32 + tid] = s;
    }
}

// ------------------------------------------------------------------- theta --
// grid (213 col-blocks, 8 map-groups). Thread owns one column x 8 maps.
__global__ __launch_bounds__(128) void theta_kernel(
    const float* __restrict__ e_w, const float* __restrict__ e_b,
    const float* __restrict__ f_w, const float* __restrict__ f_b)
{
    __shared__ float sz[8 * 32];
    int tid = threadIdx.x;
    int m0 = blockIdx.y * 8;
    for (int i = tid; i < 8 * 32; i += 128) sz[i] = g_z[m0 * 32 + i];
    __syncthreads();

    int j = blockIdx.x * 128 + tid;
    const float* W; const float* Bv; float* dst; int ncol; int jj;
    if (j < TE_SZ) { W = e_w; Bv = e_b; dst = g_te; ncol = TE_SZ; jj = j; }
    else {
        jj = j - TE_SZ;
        if (jj >= TF_SZ) return;
        W = f_w; Bv = f_b; dst = g_tf; ncol = TF_SZ;
    }

    float w[32];
    #pragma unroll
    for (int k = 0; k < 32; k++) w[k] = W[k * ncol + jj];
    float bb = Bv[jj];

    #pragma unroll
    for (int mm = 0; mm < 8; mm++) {
        const float4* zr = (const float4*)(sz + mm * 32);
        float c0 = bb, c1 = 0.f, c2 = 0.f, c3 = 0.f;
        #pragma unroll
        for (int kk = 0; kk < 8; kk++) {
            float4 z4 = zr[kk];
            c0 += z4.x * w[4 * kk + 0];
            c1 += z4.y * w[4 * kk + 1];
            c2 += z4.z * w[4 * kk + 2];
            c3 += z4.w * w[4 * kk + 3];
        }
        dst[(m0 + mm) * ncol + jj] = c0 + c1 + c2 + c3;
    }
}

// -------------------------------------------------------------------- main --
// CTA = (map, 32 samples), 256 threads / 8 warps.
//   lane = sample; e-phase: warp q -> stream st=q>>2, outputs (q&3)*16..+16
//   f-phase: warp q -> outputs q*16..+16; final 8-way reduce of ang partials.
// Fused 16-output accumulator batches: one LDS+pack per k feeds 8 FFMA2.
__global__ __launch_bounds__(256) void hyper_kernel(
    const float* __restrict__ states, float* __restrict__ out)
{
    int m = blockIdx.x;
    int cnt = g_count[m]; if (cnt > CAP) cnt = CAP;
    int base = blockIdx.y * 32;
    if (base >= cnt) return;

    int tid  = threadIdx.x;
    int lane = tid & 31;
    int q    = tid >> 5;
    int st   = q >> 2;          // e-stream: 0 = S, 1 = G
    int qq   = q & 3;
    int sidx = base + lane;
    bool valid = sidx < cnt;
    int b = g_list[m * CAP + (valid ? sidx : base)];

    const float* te = g_te + m * TE_SZ;
    const float* tf = g_tf + m * TF_SZ;

    __shared__ float sA[4096];     // 64x64 e-act / 128x32 f-act (reused)
    __shared__ float sB[4096];     // 64x64 e2 out
    __shared__ float sZ[1024];     // zf 32x32
    __shared__ float sAng[2048];   // 8 warps x 8 ang x 32 lanes

    int col = lane + st * 32;
    float2 xv = *(const float2*)(states + 4 * b + st * 2);
    int jh = qq * 16;

    // ---- e1: 2 -> 64 (leaky) ----
    #pragma unroll
    for (int j0 = 0; j0 < 16; j0 += 4) {
        int j = jh + j0;
        float4 w0 = *(const float4*)(te + j);
        float4 w1 = *(const float4*)(te + 64 + j);
        float4 bb = *(const float4*)(te + 128 + j);
        sA[(j + 0) * 64 + col] = leaky(fmaf(xv.x, w0.x, fmaf(xv.y, w1.x, bb.x)));
        sA[(j + 1) * 64 + col] = leaky(fmaf(xv.x, w0.y, fmaf(xv.y, w1.y, bb.y)));
        sA[(j + 2) * 64 + col] = leaky(fmaf(xv.x, w0.z, fmaf(xv.y, w1.z, bb.z)));
        sA[(j + 3) * 64 + col] = leaky(fmaf(xv.x, w0.w, fmaf(xv.y, w1.w, bb.w)));
    }
    __syncthreads();

    // ---- e2: 64 -> 64 (leaky), sA -> sB, 16 outputs per warp fused ----
    {
        u64 acc[8];
        const ulonglong2* bp = (const ulonglong2*)(te + 4288 + jh);
        #pragma unroll
        for (int t = 0; t < 4; t++) { ulonglong2 v = bp[t]; acc[2*t] = v.x; acc[2*t+1] = v.y; }
        #pragma unroll 8
        for (int k = 0; k < 64; k++) {
            u64 hh = pack2(sA[k * 64 + col]);
            const ulonglong2* wp = (const ulonglong2*)(te + 192 + k * 64 + jh);
            #pragma unroll
            for (int t = 0; t < 4; t++) {
                ulonglong2 w = wp[t];
                ffma2(acc[2*t], hh, w.x); ffma2(acc[2*t+1], hh, w.y);
            }
        }
        #pragma unroll
        for (int t = 0; t < 8; t++) {
            float2 r = unpack2(acc[t]);
            sB[(jh + 2*t + 0) * 64 + col] = leaky(r.x);
            sB[(jh + 2*t + 1) * 64 + col] = leaky(r.y);
        }
    }
    __syncthreads();

    // ---- e3: 64 -> 16 (no activation), sB -> sZ ----
    {
        int j = qq * 4;
        ulonglong2 bb = *(const ulonglong2*)(te + 5376 + j);
        u64 a0 = bb.x, a1 = bb.y;
        #pragma unroll 16
        for (int k = 0; k < 64; k++) {
            u64 hh = pack2(sB[k * 64 + col]);
            ulonglong2 w = *(const ulonglong2*)(te + 4352 + k * 16 + j);
            ffma2(a0, hh, w.x); ffma2(a1, hh, w.y);
        }
        int f = j + st * 16;   // e_s -> zf[0:16], e_g -> zf[16:32]
        float2 r;
        r = unpack2(a0); sZ[(f + 0) * 32 + lane] = r.x; sZ[(f + 1) * 32 + lane] = r.y;
        r = unpack2(a1); sZ[(f + 2) * 32 + lane] = r.x; sZ[(f + 3) * 32 + lane] = r.y;
    }
    __syncthreads();

    // ---- f1: 32 -> 128 (leaky), sZ -> sA (as 128x32), 16 outputs fused ----
    int jf = q * 16;
    {
        u64 acc[8];
        const ulonglong2* bp = (const ulonglong2*)(tf + 4096 + jf);
        #pragma unroll
        for (int t = 0; t < 4; t++) { ulonglong2 v = bp[t]; acc[2*t] = v.x; acc[2*t+1] = v.y; }
        #pragma unroll 8
        for (int k = 0; k < 32; k++) {
            u64 hh = pack2(sZ[k * 32 + lane]);
            const ulonglong2* wp = (const ulonglong2*)(tf + k * 128 + jf);
            #pragma unroll
            for (int t = 0; t < 4; t++) {
                ulonglong2 w = wp[t];
                ffma2(acc[2*t], hh, w.x); ffma2(acc[2*t+1], hh, w.y);
            }
        }
        #pragma unroll
        for (int t = 0; t < 8; t++) {
            float2 r = unpack2(acc[t]);
            sA[(jf + 2*t + 0) * 32 + lane] = leaky(r.x);
            sA[(jf + 2*t + 1) * 32 + lane] = leaky(r.y);
        }
    }
    __syncthreads();

    // ---- f2: 128 -> 128 (leaky) fused with f3: 128 -> 8 partials ----
    u64 g01 = 0, g23 = 0, g45 = 0, g67 = 0;
    {
        u64 acc[8];
        const ulonglong2* bp = (const ulonglong2*)(tf + 20608 + jf);
        #pragma unroll
        for (int t = 0; t < 4; t++) { ulonglong2 v = bp[t]; acc[2*t] = v.x; acc[2*t+1] = v.y; }
        #pragma unroll 8
        for (int k = 0; k < 128; k++) {
            u64 hh = pack2(sA[k * 32 + lane]);
            const ulonglong2* wp = (const ulonglong2*)(tf + 4224 + k * 128 + jf);
            #pragma unroll
            for (int t = 0; t < 4; t++) {
                ulonglong2 w = wp[t];
                ffma2(acc[2*t], hh, w.x); ffma2(acc[2*t+1], hh, w.y);
            }
        }
        float h2[16];
        #pragma unroll
        for (int t = 0; t < 8; t++) {
            float2 r = unpack2(acc[t]);
            h2[2*t] = leaky(r.x); h2[2*t+1] = leaky(r.y);
        }
        #pragma unroll
        for (int t = 0; t < 16; t++) {
            u64 hh = pack2(h2[t]);
            const ulonglong2* wp = (const ulonglong2*)(tf + 20736 + (jf + t) * 8);
            ulonglong2 wa = wp[0];
            ulonglong2 wb = wp[1];
            ffma2(g01, hh, wa.x); ffma2(g23, hh, wa.y);
            ffma2(g45, hh, wb.x); ffma2(g67, hh, wb.y);
        }
    }
    {
        float2 r;
        r = unpack2(g01); sAng[(q * 8 + 0) * 32 + lane] = r.x; sAng[(q * 8 + 1) * 32 + lane] = r.y;
        r = unpack2(g23); sAng[(q * 8 + 2) * 32 + lane] = r.x; sAng[(q * 8 + 3) * 32 + lane] = r.y;
        r = unpack2(g45); sAng[(q * 8 + 4) * 32 + lane] = r.x; sAng[(q * 8 + 5) * 32 + lane] = r.y;
        r = unpack2(g67); sAng[(q * 8 + 6) * 32 + lane] = r.x; sAng[(q * 8 + 7) * 32 + lane] = r.y;
    }
    __syncthreads();

    // ---- reduce 8 partials, bias, sin/cos: warp q owns angle index q ----
    if (valid) {
        float s = tf[21760 + q];
        #pragma unroll
        for (int w = 0; w < 8; w++) s += sAng[(w * 8 + q) * 32 + lane];
        out[b * 16 + q]     = sinf(s);
        out[b * 16 + 8 + q] = cosf(s);
    }
}

// ----------------------------------------------------------------- launch --
extern "C" void kernel_launch(void* const* d_in, const int* in_sizes, int n_in,
                              void* d_out, int out_size)
{
    const int*   indices = (const int*)  d_in[0];
    const float* states  = (const float*)d_in[1];
    const float* maps    = (const float*)d_in[2];
    const float* fc1_w   = (const float*)d_in[3];
    const float* fc1_b   = (const float*)d_in[4];
    const float* fc2_w   = (const float*)d_in[5];
    const float* fc2_b   = (const float*)d_in[6];
    const float* fc3_w   = (const float*)d_in[7];
    const float* fc3_b   = (const float*)d_in[8];
    const float* bn_w    = (const float*)d_in[9];
    const float* bn_b    = (const float*)d_in[10];
    const float* e_w     = (const float*)d_in[11];
    const float* e_b     = (const float*)d_in[12];
    const float* f_w     = (const float*)d_in[13];
    const float* f_b     = (const float*)d_in[14];
    float* out = (float*)d_out;

    trunk1_kernel<<<dim3(4, 16), 256>>>(maps, fc1_w, fc1_b);   // also zeroes g_count
    build_lists_kernel<<<(BSZ + 255) / 256, 256>>>(indices);
    trunk2_kernel<<<NMAPS, 512>>>(fc2_w, fc2_b, fc3_w, fc3_b, bn_w, bn_b);
    theta_kernel<<<dim3((TE_SZ + TF_SZ + 127) / 128, 8), 128>>>(e_w, e_b, f_w, f_b);
    hyper_kernel<<<dim3(NMAPS, CAP / 32), 256>>>(states, out);
}

// round 9
// speedup vs baseline: 1.2775x; 1.0076x over previous
#include <cuda_runtime.h>
#include <cuda_bf16.h>

// ----------------------------------------------------------------------------
// rlf_53446573032131: hypernetwork (R8)
//   K1 trunk L1 (128 CTAs) + build_lists (fused extra blocks)
//   K2 trunk L2-L4 + g_count snapshot/reset (keeps replay invariant)
//   K3 theta: column-pair FFMA2, z pre-duplicated in smem
//   K4 hyper: unroll-4 inner loops (reg-pressure fix), __sinf/__cosf
// ----------------------------------------------------------------------------

#define NMAPS 64
#define BSZ   8192
#define CAP   512

// theta_e (in=2, sz=[64,64,16]):
//   W1@0 [2][64] | b1@128 | W2@192 [64][64] | b2@4288 | W3@4352 [64][16] | b3@5376
// theta_f (in=32, sz=[128,128,8]):
//   W1@0 [32][128] | b1@4096 | W2@4224 [128][128] | b2@20608 | W3@20736 [128][8] | b3@21760
#define TE_SZ 5456
#define TF_SZ 21768
#define TE_PAIRS (TE_SZ / 2)     // 2728
#define TF_PAIRS (TF_SZ / 2)     // 10884
#define ALL_PAIRS (TE_PAIRS + TF_PAIRS)

__device__ int   g_count[NMAPS] = {0};   // zero at load; re-zeroed by trunk2 each call
__device__ int   g_cnt_snap[NMAPS];
__device__ int   g_list[NMAPS * CAP];
__device__ __align__(16) float g_a1[NMAPS * 256];
__device__ __align__(16) float g_z[NMAPS * 32];
__device__ __align__(16) float g_te[NMAPS * TE_SZ];
__device__ __align__(16) float g_tf[NMAPS * TF_SZ];

typedef unsigned long long u64;

__device__ __forceinline__ float leaky(float x) { return fmaxf(x, 0.2f * x); }

// ---- packed f32x2 helpers (Blackwell FFMA2/FADD2 path) ----
__device__ __forceinline__ void ffma2(u64& d, u64 a, u64 b) {
    asm("fma.rn.f32x2 %0, %1, %2, %0;" : "+l"(d) : "l"(a), "l"(b));
}
__device__ __forceinline__ u64 add2(u64 a, u64 b) {
    u64 d; asm("add.rn.f32x2 %0, %1, %2;" : "=l"(d) : "l"(a), "l"(b)); return d;
}
__device__ __forceinline__ u64 pack2(float x) {
    u64 r; asm("mov.b64 %0, {%1, %1};" : "=l"(r) : "f"(x)); return r;
}
__device__ __forceinline__ float2 unpack2(u64 v) {
    float2 r; asm("mov.b64 {%0, %1}, %2;" : "=f"(r.x), "=f"(r.y) : "l"(v)); return r;
}

// ------------------------------------------------- trunk L1 + build_lists --
// grid (8 output-tiles of 32, 17): y<16 = trunk1 map-groups of 4; y==16 =
// build_lists blocks. g_count is guaranteed zero on entry (trunk2 invariant).
__global__ __launch_bounds__(256) void trunk1_kernel(
    const int*   __restrict__ indices,
    const float* __restrict__ maps,
    const float* __restrict__ fc1_w, const float* __restrict__ fc1_b)
{
    int ot = blockIdx.x, mg = blockIdx.y;
    int tid = threadIdx.x;

    if (mg == 16) {                       // ---- build lists (8 blocks) ----
        int t = ot * 256 + tid;           // 0..2047
        #pragma unroll
        for (int s = t; s < BSZ; s += 2048) {
            int m = indices[s];
            int pos = atomicAdd(&g_count[m], 1);
            if (pos < CAP) g_list[m * CAP + pos] = s;
        }
        return;
    }

    __shared__ float ms[4 * 1024];
    __shared__ float red[8 * 32 * 4];

    for (int i = tid; i < 4096; i += 256) ms[i] = maps[mg * 4096 + i];
    __syncthreads();

    int ol = tid & 31, part = tid >> 5;   // 8 i-partitions of 128
    int o = ot * 32 + ol;
    float a0 = 0.f, a1 = 0.f, a2 = 0.f, a3 = 0.f;
    int i0 = part * 128;
    #pragma unroll 4
    for (int i = i0; i < i0 + 128; i++) {
        float w = fc1_w[i * 256 + o];
        a0 += ms[i] * w;
        a1 += ms[1024 + i] * w;
        a2 += ms[2048 + i] * w;
        a3 += ms[3072 + i] * w;
    }
    *(float4*)(red + (part * 32 + ol) * 4) = make_float4(a0, a1, a2, a3);
    __syncthreads();

    if (tid < 128) {
        int o2 = tid >> 2, mm = tid & 3;
        float s = fc1_b[ot * 32 + o2];
        #pragma unroll
        for (int p = 0; p < 8; p++) s += red[p * 128 + tid];
        g_a1[(mg * 4 + mm) * 256 + ot * 32 + o2] = leaky(s);
    }
}

// --------------------------------------------- trunk L2-L4 + count snapshot --
__global__ __launch_bounds__(512) void trunk2_kernel(
    const float* __restrict__ fc2_w, const float* __restrict__ fc2_b,
    const float* __restrict__ fc3_w, const float* __restrict__ fc3_b,
    const float* __restrict__ bn_w,  const float* __restrict__ bn_b)
{
    int m = blockIdx.x, tid = threadIdx.x;
    __shared__ float a1[256];
    __shared__ float red[512];
    __shared__ float a2[128];
    __shared__ float a3[128];

    if (tid == 0) {   // snapshot + reset (keeps g_count==0 invariant for next call)
        int c = g_count[m];
        g_cnt_snap[m] = (c > CAP) ? CAP : c;
        g_count[m] = 0;
    }

    if (tid < 256) a1[tid] = g_a1[m * 256 + tid];
    __syncthreads();

    {   // L2: 256 -> 128, 4 i-partitions of 64
        int o = tid & 127, p = tid >> 7;
        float c0 = 0.f, c1 = 0.f, c2 = 0.f, c3 = 0.f;
        int i0 = p * 64;
        #pragma unroll
        for (int i = i0; i < i0 + 64; i += 4) {
            c0 += a1[i + 0] * fc2_w[(i + 0) * 128 + o];
            c1 += a1[i + 1] * fc2_w[(i + 1) * 128 + o];
            c2 += a1[i + 2] * fc2_w[(i + 2) * 128 + o];
            c3 += a1[i + 3] * fc2_w[(i + 3) * 128 + o];
        }
        red[p * 128 + o] = c0 + c1 + c2 + c3;
    }
    __syncthreads();
    if (tid < 128)
        a2[tid] = leaky(red[tid] + red[128 + tid] + red[256 + tid]
                        + red[384 + tid] + fc2_b[tid]);
    __syncthreads();

    {   // L3: 128 -> 128, 4 i-partitions of 32
        int o = tid & 127, p = tid >> 7;
        float c0 = 0.f, c1 = 0.f, c2 = 0.f, c3 = 0.f;
        int i0 = p * 32;
        #pragma unroll
        for (int i = i0; i < i0 + 32; i += 4) {
            c0 += a2[i + 0] * fc3_w[(i + 0) * 128 + o];
            c1 += a2[i + 1] * fc3_w[(i + 1) * 128 + o];
            c2 += a2[i + 2] * fc3_w[(i + 2) * 128 + o];
            c3 += a2[i + 3] * fc3_w[(i + 3) * 128 + o];
        }
        red[p * 128 + o] = c0 + c1 + c2 + c3;
    }
    __syncthreads();
    if (tid < 128)
        a3[tid] = leaky(red[tid] + red[128 + tid] + red[256 + tid]
                        + red[384 + tid] + fc3_b[tid]);
    __syncthreads();

    {   // L4 (bn): 128 -> 32, 16 i-partitions of 8
        int o = tid & 31, p = tid >> 5;
        float c = 0.f;
        #pragma unroll
        for (int i = p * 8; i < p * 8 + 8; i++)
            c += a3[i] * bn_w[i * 32 + o];
        red[p * 32 + o] = c;
    }
    __syncthreads();
    if (tid < 32) {
        float s = bn_b[tid];
        #pragma unroll
        for (int p = 0; p < 16; p++) s += red[p * 32 + tid];
        g_z[m * 32 + tid] = s;
    }
}

// ------------------------------------------------------------------- theta --
// Thread owns a COLUMN PAIR (j, j+1) x 8 maps. z is pre-duplicated in smem as
// packed u64 ((z,z)), so the inner loop is LDS.128 + 4x FFMA2: ~48 inst / 64
// MACs vs ~72 / 32 in R7.
__global__ __launch_bounds__(128) void theta_kernel(
    const float* __restrict__ e_w, const float* __restrict__ e_b,
    const float* __restrict__ f_w, const float* __restrict__ f_b)
{
    __shared__ u64 szp[8 * 32];     // duplicated-packed z for 8 maps
    int tid = threadIdx.x;
    int m0 = blockIdx.y * 8;
    for (int i = tid; i < 8 * 32; i += 128) szp[i] = pack2(g_z[m0 * 32 + i]);
    __syncthreads();

    int jp = blockIdx.x * 128 + tid;       // global pair index
    const float* W; const float* Bv; float* dst; int ncol; int j;
    if (jp < TE_PAIRS) { W = e_w; Bv = e_b; dst = g_te; ncol = TE_SZ; j = 2 * jp; }
    else {
        int t = jp - TE_PAIRS;
        if (t >= TF_PAIRS) return;
        W = f_w; Bv = f_b; dst = g_tf; ncol = TF_SZ; j = 2 * t;
    }

    u64 w[32];
    #pragma unroll
    for (int k = 0; k < 32; k++) w[k] = *(const u64*)(W + k * ncol + j);
    u64 bb = *(const u64*)(Bv + j);

    #pragma unroll
    for (int mm = 0; mm < 8; mm++) {
        const ulonglong2* zp = (const ulonglong2*)(szp + mm * 32);
        u64 a0 = bb, a1 = 0, a2 = 0, a3 = 0;
        #pragma unroll
        for (int kk = 0; kk < 16; kk += 2) {
            ulonglong2 za = zp[kk], zb = zp[kk + 1];
            ffma2(a0, za.x, w[2 * kk + 0]); ffma2(a1, za.y, w[2 * kk + 1]);
            ffma2(a2, zb.x, w[2 * kk + 2]); ffma2(a3, zb.y, w[2 * kk + 3]);
        }
        *(u64*)(dst + (m0 + mm) * ncol + j) = add2(add2(a0, a1), add2(a2, a3));
    }
}

// -------------------------------------------------------------------- main --
// CTA = (map, 32 samples), 256 threads / 8 warps. unroll 4 on the weight
// loops (16 LDG.128 in flight, ~32 weight regs -- the R7 unroll-8 config
// batched up to 64, risking spills). __sinf/__cosf for the epilogue.
__global__ __launch_bounds__(256) void hyper_kernel(
    const float* __restrict__ states, float* __restrict__ out)
{
    int m = blockIdx.x;
    int cnt = g_cnt_snap[m];
    int base = blockIdx.y * 32;
    if (base >= cnt) return;

    int tid  = threadIdx.x;
    int lane = tid & 31;
    int q    = tid >> 5;
    int st   = q >> 2;          // e-stream: 0 = S, 1 = G
    int qq   = q & 3;
    int sidx = base + lane;
    bool valid = sidx < cnt;
    int b = g_list[m * CAP + (valid ? sidx : base)];

    const float* te = g_te + m * TE_SZ;
    const float* tf = g_tf + m * TF_SZ;

    __shared__ float sA[4096];     // 64x64 e-act / 128x32 f-act (reused)
    __shared__ float sB[4096];     // 64x64 e2 out
    __shared__ float sZ[1024];     // zf 32x32
    __shared__ float sAng[2048];   // 8 warps x 8 ang x 32 lanes

    int col = lane + st * 32;
    float2 xv = *(const float2*)(states + 4 * b + st * 2);
    int jh = qq * 16;

    // ---- e1: 2 -> 64 (leaky) ----
    #pragma unroll
    for (int j0 = 0; j0 < 16; j0 += 4) {
        int j = jh + j0;
        float4 w0 = *(const float4*)(te + j);
        float4 w1 = *(const float4*)(te + 64 + j);
        float4 bb = *(const float4*)(te + 128 + j);
        sA[(j + 0) * 64 + col] = leaky(fmaf(xv.x, w0.x, fmaf(xv.y, w1.x, bb.x)));
        sA[(j + 1) * 64 + col] = leaky(fmaf(xv.x, w0.y, fmaf(xv.y, w1.y, bb.y)));
        sA[(j + 2) * 64 + col] = leaky(fmaf(xv.x, w0.z, fmaf(xv.y, w1.z, bb.z)));
        sA[(j + 3) * 64 + col] = leaky(fmaf(xv.x, w0.w, fmaf(xv.y, w1.w, bb.w)));
    }
    __syncthreads();

    // ---- e2: 64 -> 64 (leaky), sA -> sB, 16 outputs per warp ----
    {
        u64 acc[8];
        const ulonglong2* bp = (const ulonglong2*)(te + 4288 + jh);
        #pragma unroll
        for (int t = 0; t < 4; t++) { ulonglong2 v = bp[t]; acc[2*t] = v.x; acc[2*t+1] = v.y; }
        #pragma unroll 4
        for (int k = 0; k < 64; k++) {
            u64 hh = pack2(sA[k * 64 + col]);
            const ulonglong2* wp = (const ulonglong2*)(te + 192 + k * 64 + jh);
            #pragma unroll
            for (int t = 0; t < 4; t++) {
                ulonglong2 w = wp[t];
                ffma2(acc[2*t], hh, w.x); ffma2(acc[2*t+1], hh, w.y);
            }
        }
        #pragma unroll
        for (int t = 0; t < 8; t++) {
            float2 r = unpack2(acc[t]);
            sB[(jh + 2*t + 0) * 64 + col] = leaky(r.x);
            sB[(jh + 2*t + 1) * 64 + col] = leaky(r.y);
        }
    }
    __syncthreads();

    // ---- e3: 64 -> 16 (no activation), sB -> sZ ----
    {
        int j = qq * 4;
        ulonglong2 bb = *(const ulonglong2*)(te + 5376 + j);
        u64 a0 = bb.x, a1 = bb.y;
        #pragma unroll 8
        for (int k = 0; k < 64; k++) {
            u64 hh = pack2(sB[k * 64 + col]);
            ulonglong2 w = *(const ulonglong2*)(te + 4352 + k * 16 + j);
            ffma2(a0, hh, w.x); ffma2(a1, hh, w.y);
        }
        int f = j + st * 16;   // e_s -> zf[0:16], e_g -> zf[16:32]
        float2 r;
        r = unpack2(a0); sZ[(f + 0) * 32 + lane] = r.x; sZ[(f + 1) * 32 + lane] = r.y;
        r = unpack2(a1); sZ[(f + 2) * 32 + lane] = r.x; sZ[(f + 3) * 32 + lane] = r.y;
    }
    __syncthreads();

    // ---- f1: 32 -> 128 (leaky), sZ -> sA (as 128x32) ----
    int jf = q * 16;
    {
        u64 acc[8];
        const ulonglong2* bp = (const ulonglong2*)(tf + 4096 + jf);
        #pragma unroll
        for (int t = 0; t < 4; t++) { ulonglong2 v = bp[t]; acc[2*t] = v.x; acc[2*t+1] = v.y; }
        #pragma unroll 4
        for (int k = 0; k < 32; k++) {
            u64 hh = pack2(sZ[k * 32 + lane]);
            const ulonglong2* wp = (const ulonglong2*)(tf + k * 128 + jf);
            #pragma unroll
            for (int t = 0; t < 4; t++) {
                ulonglong2 w = wp[t];
                ffma2(acc[2*t], hh, w.x); ffma2(acc[2*t+1], hh, w.y);
            }
        }
        #pragma unroll
        for (int t = 0; t < 8; t++) {
            float2 r = unpack2(acc[t]);
            sA[(jf + 2*t + 0) * 32 + lane] = leaky(r.x);
            sA[(jf + 2*t + 1) * 32 + lane] = leaky(r.y);
        }
    }
    __syncthreads();

    // ---- f2: 128 -> 128 (leaky) fused with f3: 128 -> 8 partials ----
    u64 g01 = 0, g23 = 0, g45 = 0, g67 = 0;
    {
        u64 acc[8];
        const ulonglong2* bp = (const ulonglong2*)(tf + 20608 + jf);
        #pragma unroll
        for (int t = 0; t < 4; t++) { ulonglong2 v = bp[t]; acc[2*t] = v.x; acc[2*t+1] = v.y; }
        #pragma unroll 4
        for (int k = 0; k < 128; k++) {
            u64 hh = pack2(sA[k * 32 + lane]);
            const ulonglong2* wp = (const ulonglong2*)(tf + 4224 + k * 128 + jf);
            #pragma unroll
            for (int t = 0; t < 4; t++) {
                ulonglong2 w = wp[t];
                ffma2(acc[2*t], hh, w.x); ffma2(acc[2*t+1], hh, w.y);
            }
        }
        float h2[16];
        #pragma unroll
        for (int t = 0; t < 8; t++) {
            float2 r = unpack2(acc[t]);
            h2[2*t] = leaky(r.x); h2[2*t+1] = leaky(r.y);
        }
        #pragma unroll 4
        for (int t = 0; t < 16; t++) {
            u64 hh = pack2(h2[t]);
            const ulonglong2* wp = (const ulonglong2*)(tf + 20736 + (jf + t) * 8);
            ulonglong2 wa = wp[0];
            ulonglong2 wb = wp[1];
            ffma2(g01, hh, wa.x); ffma2(g23, hh, wa.y);
            ffma2(g45, hh, wb.x); ffma2(g67, hh, wb.y);
        }
    }
    {
        float2 r;
        r = unpack2(g01); sAng[(q * 8 + 0) * 32 + lane] = r.x; sAng[(q * 8 + 1) * 32 + lane] = r.y;
        r = unpack2(g23); sAng[(q * 8 + 2) * 32 + lane] = r.x; sAng[(q * 8 + 3) * 32 + lane] = r.y;
        r = unpack2(g45); sAng[(q * 8 + 4) * 32 + lane] = r.x; sAng[(q * 8 + 5) * 32 + lane] = r.y;
        r = unpack2(g67); sAng[(q * 8 + 6) * 32 + lane] = r.x; sAng[(q * 8 + 7) * 32 + lane] = r.y;
    }
    __syncthreads();

    // ---- reduce 8 partials, bias, sin/cos (MUFU fast path) ----
    if (valid) {
        float s = tf[21760 + q];
        #pragma unroll
        for (int w = 0; w < 8; w++) s += sAng[(w * 8 + q) * 32 + lane];
        out[b * 16 + q]     = __sinf(s);
        out[b * 16 + 8 + q] = __cosf(s);
    }
}

// ----------------------------------------------------------------- launch --
extern "C" void kernel_launch(void* const* d_in, const int* in_sizes, int n_in,
                              void* d_out, int out_size)
{
    const int*   indices = (const int*)  d_in[0];
    const float* states  = (const float*)d_in[1];
    const float* maps    = (const float*)d_in[2];
    const float* fc1_w   = (const float*)d_in[3];
    const float* fc1_b   = (const float*)d_in[4];
    const float* fc2_w   = (const float*)d_in[5];
    const float* fc2_b   = (const float*)d_in[6];
    const float* fc3_w   = (const float*)d_in[7];
    const float* fc3_b   = (const float*)d_in[8];
    const float* bn_w    = (const float*)d_in[9];
    const float* bn_b    = (const float*)d_in[10];
    const float* e_w     = (const float*)d_in[11];
    const float* e_b     = (const float*)d_in[12];
    const float* f_w     = (const float*)d_in[13];
    const float* f_b     = (const float*)d_in[14];
    float* out = (float*)d_out;

    trunk1_kernel<<<dim3(8, 17), 256>>>(indices, maps, fc1_w, fc1_b);
    trunk2_kernel<<<NMAPS, 512>>>(fc2_w, fc2_b, fc3_w, fc3_b, bn_w, bn_b);
    theta_kernel<<<dim3((ALL_PAIRS + 127) / 128, 8), 128>>>(e_w, e_b, f_w, f_b);
    hyper_kernel<<<dim3(NMAPS, CAP / 32), 256>>>(states, out);
}

// round 10
// speedup vs baseline: 1.5703x; 1.2292x over previous
#include <cuda_runtime.h>
#include <cuda_bf16.h>

// ----------------------------------------------------------------------------
// rlf_53446573032131: hypernetwork (R9)
//   K1 trunk L1 (128 CTAs) + build_lists (fused extra blocks)
//   K2 trunk L2-L4 + g_count snapshot/reset
//   K3 theta: column-pair FFMA2, z pre-duplicated in smem
//   K4 hyper: 512 threads / 16 warps (2x occupancy vs R8), 8 outputs per warp,
//      packed-u64 smem activations for the f-phase (no per-k pack), h2 staged
//      through smem for the final angle reduction.
// ----------------------------------------------------------------------------

#define NMAPS 64
#define BSZ   8192
#define CAP   512

// theta_e (in=2, sz=[64,64,16]):
//   W1@0 [2][64] | b1@128 | W2@192 [64][64] | b2@4288 | W3@4352 [64][16] | b3@5376
// theta_f (in=32, sz=[128,128,8]):
//   W1@0 [32][128] | b1@4096 | W2@4224 [128][128] | b2@20608 | W3@20736 [128][8] | b3@21760
#define TE_SZ 5456
#define TF_SZ 21768
#define TE_PAIRS (TE_SZ / 2)     // 2728
#define TF_PAIRS (TF_SZ / 2)     // 10884
#define ALL_PAIRS (TE_PAIRS + TF_PAIRS)

__device__ int   g_count[NMAPS] = {0};   // zero at load; re-zeroed by trunk2 each call
__device__ int   g_cnt_snap[NMAPS];
__device__ int   g_list[NMAPS * CAP];
__device__ __align__(16) float g_a1[NMAPS * 256];
__device__ __align__(16) float g_z[NMAPS * 32];
__device__ __align__(16) float g_te[NMAPS * TE_SZ];
__device__ __align__(16) float g_tf[NMAPS * TF_SZ];

typedef unsigned long long u64;

__device__ __forceinline__ float leaky(float x) { return fmaxf(x, 0.2f * x); }

// ---- packed f32x2 helpers ----
__device__ __forceinline__ void ffma2(u64& d, u64 a, u64 b) {
    asm("fma.rn.f32x2 %0, %1, %2, %0;" : "+l"(d) : "l"(a), "l"(b));
}
__device__ __forceinline__ u64 add2(u64 a, u64 b) {
    u64 d; asm("add.rn.f32x2 %0, %1, %2;" : "=l"(d) : "l"(a), "l"(b)); return d;
}
__device__ __forceinline__ u64 pack2(float x) {
    u64 r; asm("mov.b64 %0, {%1, %1};" : "=l"(r) : "f"(x)); return r;
}
__device__ __forceinline__ float2 unpack2(u64 v) {
    float2 r; asm("mov.b64 {%0, %1}, %2;" : "=f"(r.x), "=f"(r.y) : "l"(v)); return r;
}

// ------------------------------------------------- trunk L1 + build_lists --
__global__ __launch_bounds__(256) void trunk1_kernel(
    const int*   __restrict__ indices,
    const float* __restrict__ maps,
    const float* __restrict__ fc1_w, const float* __restrict__ fc1_b)
{
    int ot = blockIdx.x, mg = blockIdx.y;
    int tid = threadIdx.x;

    if (mg == 16) {                       // ---- build lists (8 blocks) ----
        int t = ot * 256 + tid;           // 0..2047
        #pragma unroll
        for (int s = t; s < BSZ; s += 2048) {
            int m = indices[s];
            int pos = atomicAdd(&g_count[m], 1);
            if (pos < CAP) g_list[m * CAP + pos] = s;
        }
        return;
    }

    __shared__ float ms[4 * 1024];
    __shared__ float red[8 * 32 * 4];

    for (int i = tid; i < 4096; i += 256) ms[i] = maps[mg * 4096 + i];
    __syncthreads();

    int ol = tid & 31, part = tid >> 5;   // 8 i-partitions of 128
    int o = ot * 32 + ol;
    float a0 = 0.f, a1 = 0.f, a2 = 0.f, a3 = 0.f;
    int i0 = part * 128;
    #pragma unroll 4
    for (int i = i0; i < i0 + 128; i++) {
        float w = fc1_w[i * 256 + o];
        a0 += ms[i] * w;
        a1 += ms[1024 + i] * w;
        a2 += ms[2048 + i] * w;
        a3 += ms[3072 + i] * w;
    }
    *(float4*)(red + (part * 32 + ol) * 4) = make_float4(a0, a1, a2, a3);
    __syncthreads();

    if (tid < 128) {
        int o2 = tid >> 2, mm = tid & 3;
        float s = fc1_b[ot * 32 + o2];
        #pragma unroll
        for (int p = 0; p < 8; p++) s += red[p * 128 + tid];
        g_a1[(mg * 4 + mm) * 256 + ot * 32 + o2] = leaky(s);
    }
}

// --------------------------------------------- trunk L2-L4 + count snapshot --
__global__ __launch_bounds__(512) void trunk2_kernel(
    const float* __restrict__ fc2_w, const float* __restrict__ fc2_b,
    const float* __restrict__ fc3_w, const float* __restrict__ fc3_b,
    const float* __restrict__ bn_w,  const float* __restrict__ bn_b)
{
    int m = blockIdx.x, tid = threadIdx.x;
    __shared__ float a1[256];
    __shared__ float red[512];
    __shared__ float a2[128];
    __shared__ float a3[128];

    if (tid == 0) {
        int c = g_count[m];
        g_cnt_snap[m] = (c > CAP) ? CAP : c;
        g_count[m] = 0;
    }

    if (tid < 256) a1[tid] = g_a1[m * 256 + tid];
    __syncthreads();

    {   // L2: 256 -> 128
        int o = tid & 127, p = tid >> 7;
        float c0 = 0.f, c1 = 0.f, c2 = 0.f, c3 = 0.f;
        int i0 = p * 64;
        #pragma unroll
        for (int i = i0; i < i0 + 64; i += 4) {
            c0 += a1[i + 0] * fc2_w[(i + 0) * 128 + o];
            c1 += a1[i + 1] * fc2_w[(i + 1) * 128 + o];
            c2 += a1[i + 2] * fc2_w[(i + 2) * 128 + o];
            c3 += a1[i + 3] * fc2_w[(i + 3) * 128 + o];
        }
        red[p * 128 + o] = c0 + c1 + c2 + c3;
    }
    __syncthreads();
    if (tid < 128)
        a2[tid] = leaky(red[tid] + red[128 + tid] + red[256 + tid]
                        + red[384 + tid] + fc2_b[tid]);
    __syncthreads();

    {   // L3: 128 -> 128
        int o = tid & 127, p = tid >> 7;
        float c0 = 0.f, c1 = 0.f, c2 = 0.f, c3 = 0.f;
        int i0 = p * 32;
        #pragma unroll
        for (int i = i0; i < i0 + 32; i += 4) {
            c0 += a2[i + 0] * fc3_w[(i + 0) * 128 + o];
            c1 += a2[i + 1] * fc3_w[(i + 1) * 128 + o];
            c2 += a2[i + 2] * fc3_w[(i + 2) * 128 + o];
            c3 += a2[i + 3] * fc3_w[(i + 3) * 128 + o];
        }
        red[p * 128 + o] = c0 + c1 + c2 + c3;
    }
    __syncthreads();
    if (tid < 128)
        a3[tid] = leaky(red[tid] + red[128 + tid] + red[256 + tid]
                        + red[384 + tid] + fc3_b[tid]);
    __syncthreads();

    {   // L4 (bn): 128 -> 32
        int o = tid & 31, p = tid >> 5;
        float c = 0.f;
        #pragma unroll
        for (int i = p * 8; i < p * 8 + 8; i++)
            c += a3[i] * bn_w[i * 32 + o];
        red[p * 32 + o] = c;
    }
    __syncthreads();
    if (tid < 32) {
        float s = bn_b[tid];
        #pragma unroll
        for (int p = 0; p < 16; p++) s += red[p * 32 + tid];
        g_z[m * 32 + tid] = s;
    }
}

// ------------------------------------------------------------------- theta --
__global__ __launch_bounds__(128) void theta_kernel(
    const float* __restrict__ e_w, const float* __restrict__ e_b,
    const float* __restrict__ f_w, const float* __restrict__ f_b)
{
    __shared__ u64 szp[8 * 32];
    int tid = threadIdx.x;
    int m0 = blockIdx.y * 8;
    for (int i = tid; i < 8 * 32; i += 128) szp[i] = pack2(g_z[m0 * 32 + i]);
    __syncthreads();

    int jp = blockIdx.x * 128 + tid;
    const float* W; const float* Bv; float* dst; int ncol; int j;
    if (jp < TE_PAIRS) { W = e_w; Bv = e_b; dst = g_te; ncol = TE_SZ; j = 2 * jp; }
    else {
        int t = jp - TE_PAIRS;
        if (t >= TF_PAIRS) return;
        W = f_w; Bv = f_b; dst = g_tf; ncol = TF_SZ; j = 2 * t;
    }

    u64 w[32];
    #pragma unroll
    for (int k = 0; k < 32; k++) w[k] = *(const u64*)(W + k * ncol + j);
    u64 bb = *(const u64*)(Bv + j);

    #pragma unroll
    for (int mm = 0; mm < 8; mm++) {
        const ulonglong2* zp = (const ulonglong2*)(szp + mm * 32);
        u64 a0 = bb, a1 = 0, a2 = 0, a3 = 0;
        #pragma unroll
        for (int kk = 0; kk < 16; kk += 2) {
            ulonglong2 za = zp[kk], zb = zp[kk + 1];
            ffma2(a0, za.x, w[2 * kk + 0]); ffma2(a1, za.y, w[2 * kk + 1]);
            ffma2(a2, zb.x, w[2 * kk + 2]); ffma2(a3, zb.y, w[2 * kk + 3]);
        }
        *(u64*)(dst + (m0 + mm) * ncol + j) = add2(add2(a0, a1), add2(a2, a3));
    }
}

// -------------------------------------------------------------------- main --
// CTA = (map, 32 samples), 512 threads / 16 warps (R8 had 8: occ 23.8%,
// issue 9.3% -> latency-starved). Finer output split: 8 outputs/warp in
// e1/e2/f1/f2, 2 in e3. f-phase activations pre-packed u64 in smem.
// smem: X 32KB (e: sE 16KB + sB 16KB; f: sFp u64[128][32]; tail: h2s 16KB),
//       Zp 8KB. Total 40KB static.
__global__ __launch_bounds__(512) void hyper_kernel(
    const float* __restrict__ states, float* __restrict__ out)
{
    int m = blockIdx.x;
    int cnt = g_cnt_snap[m];
    int base = blockIdx.y * 32;
    if (base >= cnt) return;

    int tid  = threadIdx.x;
    int lane = tid & 31;
    int w    = tid >> 5;        // 0..15
    int st   = w >> 3;          // e-stream: 0 = S, 1 = G
    int wq   = w & 7;           // warp-in-stream
    int sidx = base + lane;
    bool valid = sidx < cnt;
    int b = g_list[m * CAP + (valid ? sidx : base)];

    const float* te = g_te + m * TE_SZ;
    const float* tf = g_tf + m * TF_SZ;

    __shared__ __align__(16) u64 X[4096];    // 32KB multi-purpose
    __shared__ __align__(16) u64 Zp[1024];   // zf packed [32][32]

    float* sE  = (float*)X;          // [64][64] e1 out
    float* sB  = ((float*)X) + 4096; // [64][64] e2 out
    u64*   sFp = X;                  // [128][32] f1 out (packed)
    float* h2s = (float*)X;          // [128][32] f2 out

    int col = lane + st * 32;
    float2 xv = *(const float2*)(states + 4 * b + st * 2);
    int jh = wq * 8;

    // ---- e1: 2 -> 64 (leaky) ----
    #pragma unroll
    for (int j0 = 0; j0 < 8; j0 += 4) {
        int j = jh + j0;
        float4 w0 = *(const float4*)(te + j);
        float4 w1 = *(const float4*)(te + 64 + j);
        float4 bb = *(const float4*)(te + 128 + j);
        sE[(j + 0) * 64 + col] = leaky(fmaf(xv.x, w0.x, fmaf(xv.y, w1.x, bb.x)));
        sE[(j + 1) * 64 + col] = leaky(fmaf(xv.x, w0.y, fmaf(xv.y, w1.y, bb.y)));
        sE[(j + 2) * 64 + col] = leaky(fmaf(xv.x, w0.z, fmaf(xv.y, w1.z, bb.z)));
        sE[(j + 3) * 64 + col] = leaky(fmaf(xv.x, w0.w, fmaf(xv.y, w1.w, bb.w)));
    }
    __syncthreads();

    // ---- e2: 64 -> 64 (leaky), sE -> sB, 8 outputs/warp ----
    {
        u64 acc[4];
        {
            const ulonglong2* bp = (const ulonglong2*)(te + 4288 + jh);
            ulonglong2 v0 = bp[0], v1 = bp[1];
            acc[0] = v0.x; acc[1] = v0.y; acc[2] = v1.x; acc[3] = v1.y;
        }
        #pragma unroll 4
        for (int k = 0; k < 64; k++) {
            u64 hh = pack2(sE[k * 64 + col]);
            const ulonglong2* wp = (const ulonglong2*)(te + 192 + k * 64 + jh);
            ulonglong2 w0 = wp[0], w1 = wp[1];
            ffma2(acc[0], hh, w0.x); ffma2(acc[1], hh, w0.y);
            ffma2(acc[2], hh, w1.x); ffma2(acc[3], hh, w1.y);
        }
        #pragma unroll
        for (int t = 0; t < 4; t++) {
            float2 r = unpack2(acc[t]);
            sB[(jh + 2*t + 0) * 64 + col] = leaky(r.x);
            sB[(jh + 2*t + 1) * 64 + col] = leaky(r.y);
        }
    }
    __syncthreads();

    // ---- e3: 64 -> 16 (no act), sB -> Zp (packed), 2 outputs/warp ----
    {
        int j = wq * 2;
        u64 a0 = *(const u64*)(te + 5376 + j);
        u64 a1 = 0;
        #pragma unroll 8
        for (int k = 0; k < 64; k += 2) {
            u64 h0 = pack2(sB[k * 64 + col]);
            u64 h1 = pack2(sB[(k + 1) * 64 + col]);
            u64 w0 = *(const u64*)(te + 4352 + k * 16 + j);
            u64 w1 = *(const u64*)(te + 4352 + (k + 1) * 16 + j);
            ffma2(a0, h0, w0); ffma2(a1, h1, w1);
        }
        float2 r = unpack2(add2(a0, a1));
        int f = j + st * 16;     // e_s -> zf[0:16], e_g -> zf[16:32]
        Zp[(f + 0) * 32 + lane] = pack2(r.x);
        Zp[(f + 1) * 32 + lane] = pack2(r.y);
    }
    __syncthreads();

    // ---- f1: 32 -> 128 (leaky), Zp -> sFp (packed), 8 outputs/warp ----
    int jf = w * 8;
    {
        u64 acc[4];
        {
            const ulonglong2* bp = (const ulonglong2*)(tf + 4096 + jf);
            ulonglong2 v0 = bp[0], v1 = bp[1];
            acc[0] = v0.x; acc[1] = v0.y; acc[2] = v1.x; acc[3] = v1.y;
        }
        #pragma unroll 4
        for (int k = 0; k < 32; k++) {
            u64 hh = Zp[k * 32 + lane];
            const ulonglong2* wp = (const ulonglong2*)(tf + k * 128 + jf);
            ulonglong2 w0 = wp[0], w1 = wp[1];
            ffma2(acc[0], hh, w0.x); ffma2(acc[1], hh, w0.y);
            ffma2(acc[2], hh, w1.x); ffma2(acc[3], hh, w1.y);
        }
        // write AFTER all warps finished reading sE/sB region? f1 writes sFp
        // which overlays sE/sB -- but e-phase reads ended at the previous
        // __syncthreads(), so this is safe.
        #pragma unroll
        for (int t = 0; t < 4; t++) {
            float2 r = unpack2(acc[t]);
            sFp[(jf + 2*t + 0) * 32 + lane] = pack2(leaky(r.x));
            sFp[(jf + 2*t + 1) * 32 + lane] = pack2(leaky(r.y));
        }
    }
    __syncthreads();

    // ---- f2: 128 -> 128 (leaky), 8 outputs/warp, h2 kept in regs ----
    float h2[8];
    {
        u64 acc[4];
        {
            const ulonglong2* bp = (const ulonglong2*)(tf + 20608 + jf);
            ulonglong2 v0 = bp[0], v1 = bp[1];
            acc[0] = v0.x; acc[1] = v0.y; acc[2] = v1.x; acc[3] = v1.y;
        }
        #pragma unroll 4
        for (int k = 0; k < 128; k++) {
            u64 hh = sFp[k * 32 + lane];
            const ulonglong2* wp = (const ulonglong2*)(tf + 4224 + k * 128 + jf);
            ulonglong2 w0 = wp[0], w1 = wp[1];
            ffma2(acc[0], hh, w0.x); ffma2(acc[1], hh, w0.y);
            ffma2(acc[2], hh, w1.x); ffma2(acc[3], hh, w1.y);
        }
        #pragma unroll
        for (int t = 0; t < 4; t++) {
            float2 r = unpack2(acc[t]);
            h2[2*t]     = leaky(r.x);
            h2[2*t + 1] = leaky(r.y);
        }
    }
    __syncthreads();            // everyone done READING sFp
    #pragma unroll
    for (int t = 0; t < 8; t++) h2s[(jf + t) * 32 + lane] = h2[t];
    __syncthreads();

    // ---- f3: 128 -> 8, warp r (<8) computes angle r; sin/cos epilogue ----
    if (w < 8 && valid) {
        int r = w;
        float s = tf[21760 + r];
        #pragma unroll 8
        for (int j = 0; j < 128; j++)
            s = fmaf(h2s[j * 32 + lane], tf[20736 + j * 8 + r], s);
        out[b * 16 + r]     = __sinf(s);
        out[b * 16 + 8 + r] = __cosf(s);
    }
}

// ----------------------------------------------------------------- launch --
extern "C" void kernel_launch(void* const* d_in, const int* in_sizes, int n_in,
                              void* d_out, int out_size)
{
    const int*   indices = (const int*)  d_in[0];
    const float* states  = (const float*)d_in[1];
    const float* maps    = (const float*)d_in[2];
    const float* fc1_w   = (const float*)d_in[3];
    const float* fc1_b   = (const float*)d_in[4];
    const float* fc2_w   = (const float*)d_in[5];
    const float* fc2_b   = (const float*)d_in[6];
    const float* fc3_w   = (const float*)d_in[7];
    const float* fc3_b   = (const float*)d_in[8];
    const float* bn_w    = (const float*)d_in[9];
    const float* bn_b    = (const float*)d_in[10];
    const float* e_w     = (const float*)d_in[11];
    const float* e_b     = (const float*)d_in[12];
    const float* f_w     = (const float*)d_in[13];
    const float* f_b     = (const float*)d_in[14];
    float* out = (float*)d_out;

    trunk1_kernel<<<dim3(8, 17), 256>>>(indices, maps, fc1_w, fc1_b);
    trunk2_kernel<<<NMAPS, 512>>>(fc2_w, fc2_b, fc3_w, fc3_b, bn_w, bn_b);
    theta_kernel<<<dim3((ALL_PAIRS + 127) / 128, 8), 128>>>(e_w, e_b, f_w, f_b);
    hyper_kernel<<<dim3(NMAPS, CAP / 32), 512>>>(states, out);
}